// round 8
// baseline (speedup 1.0000x reference)
#include <cuda_runtime.h>
#include <float.h>

// x: [B=64, N=4096, D=1024] fp32, top-K=16 along N per (b,d), then mean -> out [B, D] fp32.
// One thread per (b,d) column. Warp lanes span consecutive d -> fully coalesced
// 128B accesses. Top-16 kept as a sorted register array; hot path is a single
// compare against the current 16th-largest value.

#define B_DIM 64
#define N_DIM 4096
#define D_DIM 1024
#define K_TOP 16
#define NCOL (B_DIM * D_DIM)   // 65536 threads total
#define TPB 256
#define UNROLL 16

__global__ __launch_bounds__(TPB, 4)
void topk_mean_kernel(const float* __restrict__ x, float* __restrict__ out) {
    const int tid = blockIdx.x * TPB + threadIdx.x;
    const int b = tid >> 10;        // tid / 1024
    const int d = tid & 1023;       // tid % 1024

    const float* __restrict__ col = x + ((size_t)b * N_DIM) * D_DIM + d;

    // Sorted descending: top[0] >= top[1] >= ... >= top[15]
    float top[K_TOP];
#pragma unroll
    for (int j = 0; j < K_TOP; ++j) top[j] = -FLT_MAX;

#pragma unroll 1
    for (int n = 0; n < N_DIM; n += UNROLL) {
        // Batch UNROLL independent loads for MLP; offsets are compile-time
        // immediates (u * 4096 B) off an advancing base pointer.
        float buf[UNROLL];
#pragma unroll
        for (int u = 0; u < UNROLL; ++u)
            buf[u] = __ldg(col + (size_t)u * D_DIM);
        col += (size_t)UNROLL * D_DIM;

#pragma unroll
        for (int u = 0; u < UNROLL; ++u) {
            float v = buf[u];
            if (v > top[K_TOP - 1]) {
                // Bubble v into place (branchless compare-swap chain,
                // all constant indices -> stays in registers).
                top[K_TOP - 1] = v;
#pragma unroll
                for (int j = K_TOP - 1; j > 0; --j) {
                    float hi = fmaxf(top[j - 1], top[j]);
                    float lo = fminf(top[j - 1], top[j]);
                    top[j - 1] = hi;
                    top[j] = lo;
                }
            }
        }
    }

    float s = 0.0f;
#pragma unroll
    for (int j = 0; j < K_TOP; ++j) s += top[j];
    out[tid] = s * (1.0f / K_TOP);
}

extern "C" void kernel_launch(void* const* d_in, const int* in_sizes, int n_in,
                              void* d_out, int out_size) {
    const float* x = (const float*)d_in[0];
    float* out = (float*)d_out;
    topk_mean_kernel<<<NCOL / TPB, TPB>>>(x, out);
}

// round 9
// speedup vs baseline: 1.0016x; 1.0016x over previous
#include <cuda_runtime.h>
#include <float.h>

// x: [B=64, N=4096, D=1024] fp32, top-K=16 along N per (b,d), then mean -> out [B, D] fp32.
// One thread per (b,d) column. Warp lanes span consecutive d -> fully coalesced
// 128B accesses. Top-16 kept as a sorted register array; hot path is a single
// compare against the current 16th-largest value.

#define B_DIM 64
#define N_DIM 4096
#define D_DIM 1024
#define K_TOP 16
#define NCOL (B_DIM * D_DIM)   // 65536 threads total
#define TPB 256
#define UNROLL 16

__global__ __launch_bounds__(TPB, 4)
void topk_mean_kernel(const float* __restrict__ x, float* __restrict__ out) {
    const int tid = blockIdx.x * TPB + threadIdx.x;
    const int b = tid >> 10;        // tid / 1024
    const int d = tid & 1023;       // tid % 1024

    const float* __restrict__ col = x + ((size_t)b * N_DIM) * D_DIM + d;

    // Sorted descending: top[0] >= top[1] >= ... >= top[15]
    float top[K_TOP];
#pragma unroll
    for (int j = 0; j < K_TOP; ++j) top[j] = -FLT_MAX;

#pragma unroll 1
    for (int n = 0; n < N_DIM; n += UNROLL) {
        // Batch UNROLL independent loads for MLP; offsets are compile-time
        // immediates (u * 4096 B) off an advancing base pointer.
        float buf[UNROLL];
#pragma unroll
        for (int u = 0; u < UNROLL; ++u)
            buf[u] = __ldg(col + (size_t)u * D_DIM);
        col += (size_t)UNROLL * D_DIM;

#pragma unroll
        for (int u = 0; u < UNROLL; ++u) {
            float v = buf[u];
            if (v > top[K_TOP - 1]) {
                // Bubble v into place (branchless compare-swap chain,
                // all constant indices -> stays in registers).
                top[K_TOP - 1] = v;
#pragma unroll
                for (int j = K_TOP - 1; j > 0; --j) {
                    float hi = fmaxf(top[j - 1], top[j]);
                    float lo = fminf(top[j - 1], top[j]);
                    top[j - 1] = hi;
                    top[j] = lo;
                }
            }
        }
    }

    float s = 0.0f;
#pragma unroll
    for (int j = 0; j < K_TOP; ++j) s += top[j];
    out[tid] = s * (1.0f / K_TOP);
}

extern "C" void kernel_launch(void* const* d_in, const int* in_sizes, int n_in,
                              void* d_out, int out_size) {
    const float* x = (const float*)d_in[0];
    float* out = (float*)d_out;
    topk_mean_kernel<<<NCOL / TPB, TPB>>>(x, out);
}